// round 3
// baseline (speedup 1.0000x reference)
#include <cuda_runtime.h>
#include <cuda_bf16.h>

// y[b] = sum_{s=0}^{21} w[s] * f_s(x[b,:]).
// Segment s: candidates (m, l=s-3m), l in [0,16); priority = largest m.
// Candidate valid iff x[m] in (phi-iv[m], phi+iv[m]]  (diff in (-iv, iv]).
// f_s = 0.5*cos(x[m*]-phi*) + 0.5 for selected candidate, else 0.
// Output: [ y (batch floats), weight (48 floats) ].

#define TPB 256
#define RPT 8

__global__ void __launch_bounds__(TPB, 3)
glm_kernel(const float* __restrict__ x,
           const float* __restrict__ phis,
           const float* __restrict__ interval,
           const float* __restrict__ weight,
           float* __restrict__ out,
           int batch) {
    // per candidate: (lo, hi, phi, pad) -> single LDS.128
    __shared__ float4 sc[48];
    __shared__ float  shw[22];

    const int t = threadIdx.x;
    if (t < 48) {
        const float p  = phis[t];
        const float iv = interval[t >> 4];
        sc[t] = make_float4(p - iv, p + iv, p, 0.0f);
    }
    if (t < 22) shw[t] = 0.5f * weight[t];
    if (blockIdx.x == 0 && t < 48) out[batch + t] = weight[t];  // weight tail
    __syncthreads();

    const int tid = blockIdx.x * TPB + t;
    const long long r0 = (long long)tid * RPT;
    if (r0 >= batch) return;

    // 8 rows * 3 floats = 96B = 6 x float4 (aligned: r0*3 = 24*tid)
    const float4* xv = reinterpret_cast<const float4*>(x + r0 * 3);
    float4 v0 = xv[0], v1 = xv[1], v2 = xv[2], v3 = xv[3], v4 = xv[4], v5 = xv[5];

    float X[RPT][3] = {
        {v0.x, v0.y, v0.z}, {v0.w, v1.x, v1.y},
        {v1.z, v1.w, v2.x}, {v2.y, v2.z, v2.w},
        {v3.x, v3.y, v3.z}, {v3.w, v4.x, v4.y},
        {v4.z, v4.w, v5.x}, {v5.y, v5.z, v5.w}
    };
    float yc[RPT], wa[RPT];
#pragma unroll
    for (int r = 0; r < RPT; ++r) { yc[r] = 0.0f; wa[r] = 0.0f; }

    // s = 0..2 : only m=0 (cand l=s)
#pragma unroll
    for (int s = 0; s < 3; ++s) {
        const float4 A = sc[s];
        const float hw = shw[s];
#pragma unroll
        for (int r = 0; r < RPT; ++r) {
            const float xa = X[r][0];
            const bool  pa = (xa > A.x) && (xa <= A.y);
            const float w  = pa ? hw : 0.0f;
            yc[r] = fmaf(w, __cosf(xa - A.z), yc[r]);
            wa[r] += w;
        }
    }

    // s = 3..5 : m=1 (pri), m=0
#pragma unroll
    for (int s = 3; s < 6; ++s) {
        const float4 A = sc[16 + (s - 3)];
        const float4 B = sc[s];
        const float hw = shw[s];
#pragma unroll
        for (int r = 0; r < RPT; ++r) {
            const float xa = X[r][1], xb = X[r][0];
            const bool pa = (xa > A.x) && (xa <= A.y);
            const bool pb = (xb > B.x) && (xb <= B.y);
            const float da = xa - A.z, db = xb - B.z;
            const float d  = pa ? da : db;
            const float w  = (pa || pb) ? hw : 0.0f;
            yc[r] = fmaf(w, __cosf(d), yc[r]);
            wa[r] += w;
        }
    }

    // s = 6..15 : m=2 (pri), m=1, m=0
#pragma unroll
    for (int s = 6; s < 16; ++s) {
        const float4 A = sc[32 + (s - 6)];
        const float4 B = sc[16 + (s - 3)];
        const float4 C = sc[s];
        const float hw = shw[s];
#pragma unroll
        for (int r = 0; r < RPT; ++r) {
            const float xa = X[r][2], xb = X[r][1], xc = X[r][0];
            const bool pa = (xa > A.x) && (xa <= A.y);
            const bool pb = (xb > B.x) && (xb <= B.y);
            const bool pc = (xc > C.x) && (xc <= C.y);
            const float da = xa - A.z, db = xb - B.z, dc = xc - C.z;
            float d = pb ? db : dc;
            d = pa ? da : d;
            const float w = (pa || pb || pc) ? hw : 0.0f;
            yc[r] = fmaf(w, __cosf(d), yc[r]);
            wa[r] += w;
        }
    }

    // s = 16..18 : m=2 (pri), m=1
#pragma unroll
    for (int s = 16; s < 19; ++s) {
        const float4 A = sc[32 + (s - 6)];
        const float4 B = sc[16 + (s - 3)];
        const float hw = shw[s];
#pragma unroll
        for (int r = 0; r < RPT; ++r) {
            const float xa = X[r][2], xb = X[r][1];
            const bool pa = (xa > A.x) && (xa <= A.y);
            const bool pb = (xb > B.x) && (xb <= B.y);
            const float da = xa - A.z, db = xb - B.z;
            const float d  = pa ? da : db;
            const float w  = (pa || pb) ? hw : 0.0f;
            yc[r] = fmaf(w, __cosf(d), yc[r]);
            wa[r] += w;
        }
    }

    // s = 19..21 : only m=2
#pragma unroll
    for (int s = 19; s < 22; ++s) {
        const float4 A = sc[32 + (s - 6)];
        const float hw = shw[s];
#pragma unroll
        for (int r = 0; r < RPT; ++r) {
            const float xa = X[r][2];
            const bool  pa = (xa > A.x) && (xa <= A.y);
            const float w  = pa ? hw : 0.0f;
            yc[r] = fmaf(w, __cosf(xa - A.z), yc[r]);
            wa[r] += w;
        }
    }

    float4 o0 = make_float4(yc[0] + wa[0], yc[1] + wa[1], yc[2] + wa[2], yc[3] + wa[3]);
    float4 o1 = make_float4(yc[4] + wa[4], yc[5] + wa[5], yc[6] + wa[6], yc[7] + wa[7]);
    float4* op = reinterpret_cast<float4*>(out);
    op[2 * tid]     = o0;
    op[2 * tid + 1] = o1;
}

extern "C" void kernel_launch(void* const* d_in, const int* in_sizes, int n_in,
                              void* d_out, int out_size) {
    const float* x        = (const float*)d_in[0];
    const float* phis     = (const float*)d_in[1];
    const float* interval = (const float*)d_in[2];
    const float* weight   = (const float*)d_in[3];
    float* out = (float*)d_out;

    const int batch = in_sizes[0] / 3;
    const int n_threads = (batch + RPT - 1) / RPT;
    const int n_blocks  = (n_threads + TPB - 1) / TPB;

    glm_kernel<<<n_blocks, TPB>>>(x, phis, interval, weight, out, batch);
}

// round 4
// speedup vs baseline: 1.0837x; 1.0837x over previous
#include <cuda_runtime.h>
#include <cuda_bf16.h>

// y[b] = sum over segments s=0..21 of w[s] * f_s, where f_s selects the
// highest-m valid candidate (m,l=s-3m) with x[m] in (phi-iv, phi+iv], giving
// 0.5*cos(x[m]-phi)+0.5. Rewritten per row as
//   y = sum_m  C_m*cos(x_m) + S_m*sin(x_m) + T_m
// with (C,S,T) per m depending only on the rank triple (r0,r1,r2) of x[m]
// among the sorted window bounds of m. Coefficients precomputed per launch.
// Output: [ y (batch floats), weight (48 floats) ].

#define TPB 256
#define RPT 4

__device__ float    gSortedB[96];    // [m*32 + pos]
__device__ unsigned gSH[3][33];      // segment-space hitmask per (m, rank)
__device__ float4   gVc0[16];        // m=0 cand values (0.5w*cosphi, 0.5w*sinphi, 0.5w)
__device__ float4   gA2[33];
__device__ float4   gA1[1089];       // [r1*33 + r2]
__device__ float4   gA0[35937];      // [(r0*33 + r1)*33 + r2]

// ---------------- setup kernel A: sort bounds, masks, A1/A2 tables ----------
__global__ void setupA(const float* __restrict__ phis,
                       const float* __restrict__ interval,
                       const float* __restrict__ weight) {
    __shared__ float    sv[96];          // bound values: i<16 lo_l, i>=16 hi_l
    __shared__ int      spos[96];        // sorted position of each bound
    __shared__ float    svc[3][3][16];   // [m][{cos,sin,t}][l]
    __shared__ unsigned sSH[3][33];
    const int t = threadIdx.x;           // 128 threads

    if (t < 96) {
        const int m = t >> 5, i = t & 31, l = i & 15;
        const float p  = phis[m * 16 + l];
        const float iv = interval[m];
        sv[t] = (i < 16) ? (p - iv) : (p + iv);
    }
    if (t < 48) {
        const int m = t >> 4, l = t & 15;
        const float w = 0.5f * weight[3 * m + l];     // segment s = 3m + l
        const float p = phis[m * 16 + l];
        svc[m][0][l] = w * cosf(p);
        svc[m][1][l] = w * sinf(p);
        svc[m][2][l] = w;
    }
    __syncthreads();

    // stable rank-sort of the 32 bounds of each m
    if (t < 96) {
        const int m = t >> 5, i = t & 31;
        const float v = sv[t];
        int pos = 0;
        for (int j = 0; j < 32; ++j) {
            const float u = sv[(m << 5) + j];
            pos += (u < v || (u == v && j < i)) ? 1 : 0;
        }
        spos[t] = pos;
        gSortedB[(m << 5) + pos] = v;
    }
    __syncthreads();

    // hitmask per rank r: cond_l  <=>  pos(lo_l) < r  &&  pos(hi_l) >= r
    if (t < 99) {
        const int m = t / 33, r = t - m * 33;
        unsigned mask = 0;
        for (int l = 0; l < 16; ++l) {
            const int plo = spos[(m << 5) + l];
            const int phi_ = spos[(m << 5) + 16 + l];
            if (plo < r && phi_ >= r) mask |= (1u << l);
        }
        const unsigned sh = mask << (3 * m);   // segment space
        gSH[m][r] = sh;
        sSH[m][r] = sh;
    }
    if (t < 16) gVc0[t] = make_float4(svc[0][0][t], svc[0][1][t], svc[0][2][t], 0.0f);
    __syncthreads();

    // A2[r2]: winners W2 = SH2
    if (t < 33) {
        const unsigned mask = sSH[2][t];
        float C = 0.0f, S = 0.0f, T = 0.0f;
        for (int l = 0; l < 16; ++l)
            if (mask & (1u << (6 + l))) { C += svc[2][0][l]; S += svc[2][1][l]; T += svc[2][2][l]; }
        gA2[t] = make_float4(C, S, T, 0.0f);
    }
    // A1[r1][r2]: winners W1 = SH1 & ~SH2
    for (int e = t; e < 1089; e += blockDim.x) {
        const int r1 = e / 33, r2 = e - r1 * 33;
        const unsigned mask = sSH[1][r1] & ~sSH[2][r2];
        float C = 0.0f, S = 0.0f, T = 0.0f;
        for (int l = 0; l < 16; ++l)
            if (mask & (1u << (3 + l))) { C += svc[1][0][l]; S += svc[1][1][l]; T += svc[1][2][l]; }
        gA1[e] = make_float4(C, S, T, 0.0f);
    }
}

// ---------------- setup kernel B: triple table A0 ---------------------------
__global__ void setupB() {
    const int e = blockIdx.x * blockDim.x + threadIdx.x;
    if (e >= 35937) return;
    const int r0 = e / 1089;
    const int rem = e - r0 * 1089;
    const int r1 = rem / 33;
    const int r2 = rem - r1 * 33;
    const unsigned mask = gSH[0][r0] & ~gSH[1][r1] & ~gSH[2][r2];  // W0, bits 0..15
    float C = 0.0f, S = 0.0f, T = 0.0f;
    for (int l = 0; l < 16; ++l)
        if (mask & (1u << l)) { const float4 v = gVc0[l]; C += v.x; S += v.y; T += v.z; }
    gA0[e] = make_float4(C, S, T, 0.0f);
}

// ---------------- main kernel ----------------------------------------------
// rank = #{bounds < x} in [0,32] via branchless binary search (6 dependent steps)
__device__ __forceinline__ int rank32(const float* __restrict__ b, float xv) {
    int r = 0;
    if (b[15]    < xv) r = 16;
    if (b[r + 7] < xv) r += 8;
    if (b[r + 3] < xv) r += 4;
    if (b[r + 1] < xv) r += 2;
    if (b[r]     < xv) r += 1;
    if (b[r]     < xv) r += 1;
    return r;
}

__global__ void __launch_bounds__(TPB)
glm_main(const float* __restrict__ x,
         const float* __restrict__ weight,
         float* __restrict__ out, int batch) {
    __shared__ float  sb[96];
    __shared__ float4 sA2[33];
    __shared__ float4 sA1[1089];

    const int t = threadIdx.x;
    if (t < 96) sb[t] = gSortedB[t];
    if (t < 33) sA2[t] = gA2[t];
    for (int i = t; i < 1089; i += TPB) sA1[i] = gA1[i];
    if (blockIdx.x == 0 && t < 48) out[batch + t] = weight[t];   // weight tail
    __syncthreads();

    const int tid = blockIdx.x * TPB + t;
    const long long row0 = (long long)tid * RPT;
    if (row0 >= batch) return;

    // 4 rows * 3 floats = 48B = 3 x float4 (16B aligned)
    const float4* xv = reinterpret_cast<const float4*>(x + row0 * 3);
    const float4 va = xv[0], vb = xv[1], vc = xv[2];
    const float X[RPT][3] = {
        {va.x, va.y, va.z}, {va.w, vb.x, vb.y},
        {vb.z, vb.w, vc.x}, {vc.y, vc.z, vc.w}
    };
    float Y[RPT];

#pragma unroll
    for (int r = 0; r < RPT; ++r) {
        const int ra = rank32(sb,      X[r][0]);
        const int rb = rank32(sb + 32, X[r][1]);
        const int rc = rank32(sb + 64, X[r][2]);
        const int t12 = rb * 33 + rc;
        const float4 A1v = sA1[t12];
        const float4 A2v = sA2[rc];
        const float4 A0v = gA0[ra * 1089 + t12];
        float s0, c0, s1, c1, s2, c2;
        __sincosf(X[r][0], &s0, &c0);
        __sincosf(X[r][1], &s1, &c1);
        __sincosf(X[r][2], &s2, &c2);
        float y = (A0v.z + A1v.z) + A2v.z;
        y = fmaf(c0, A0v.x, y); y = fmaf(s0, A0v.y, y);
        y = fmaf(c1, A1v.x, y); y = fmaf(s1, A1v.y, y);
        y = fmaf(c2, A2v.x, y); y = fmaf(s2, A2v.y, y);
        Y[r] = y;
    }

    reinterpret_cast<float4*>(out)[tid] = make_float4(Y[0], Y[1], Y[2], Y[3]);
}

extern "C" void kernel_launch(void* const* d_in, const int* in_sizes, int n_in,
                              void* d_out, int out_size) {
    const float* x        = (const float*)d_in[0];
    const float* phis     = (const float*)d_in[1];
    const float* interval = (const float*)d_in[2];
    const float* weight   = (const float*)d_in[3];
    float* out = (float*)d_out;

    const int batch = in_sizes[0] / 3;
    const int n_threads = (batch + RPT - 1) / RPT;
    const int n_blocks  = (n_threads + TPB - 1) / TPB;

    setupA<<<1, 128>>>(phis, interval, weight);
    setupB<<<(35937 + 255) / 256, 256>>>();
    glm_main<<<n_blocks, TPB>>>(x, weight, out, batch);
}

// round 5
// speedup vs baseline: 1.2433x; 1.1472x over previous
#include <cuda_runtime.h>
#include <cuda_bf16.h>

// y[b] = sum over segments s=0..21 of w[s]*f_s; f_s picks highest-m valid
// candidate (m, l=s-3m) with x[m] in (phi-iv[m], phi+iv[m]], value
// 0.5*cos(x[m]-phi)+0.5. Per row this collapses to
//   y = C0*cos(x0)+S0*sin(x0)+C1*cos(x1)+S1*sin(x1)+C2*cos(x2)+S2*sin(x2)+T
// where the 7 coefficients depend only on the rank triple (r0,r1,r2) of the
// x[m] among each m's 32 sorted window bounds. One fused setup kernel builds
// the 33^3-entry coefficient table (32B/entry, L2-resident); the main kernel
// does 3 branchless rank searches + 1 gather + 3 sincos per row.
// Output: [ y (batch floats), weight (48 floats) ].

#define TPB 256
#define RPT 4
#define NR   33
#define NTAB (NR * NR * NR)   // 35937

struct __align__(32) Coef { float4 a, b; };   // a={C0,S0,C1,S1} b={C2,S2,T,0}

__device__ float gSortedB[96];                // [m*32 + pos]
__device__ Coef  gC[NTAB];                    // [(r0*33+r1)*33+r2]

// ---------------- fused setup: every block recomputes masks, fills a slice --
__global__ void __launch_bounds__(TPB)
setup_all(const float* __restrict__ phis,
          const float* __restrict__ interval,
          const float* __restrict__ weight) {
    __shared__ float    sv[96];           // bounds: i<16 -> lo_l, i>=16 -> hi_l
    __shared__ int      spos[96];         // sorted position of each bound
    __shared__ float    svc[3][3][16];    // [m][{c,s,t}][l]
    __shared__ unsigned sSH[3][NR];       // segment-space hitmask per (m, rank)

    const int t = threadIdx.x;

    if (t < 96) {
        const int m = t >> 5, i = t & 31, l = i & 15;
        const float p  = phis[m * 16 + l];
        const float iv = interval[m];
        sv[t] = (i < 16) ? (p - iv) : (p + iv);
    }
    if (t < 48) {
        const int m = t >> 4, l = t & 15;
        const float w = 0.5f * weight[3 * m + l];     // segment s = 3m + l
        const float p = phis[m * 16 + l];
        float sp, cp;
        sincosf(p, &sp, &cp);
        svc[m][0][l] = w * cp;
        svc[m][1][l] = w * sp;
        svc[m][2][l] = w;
    }
    __syncthreads();

    // stable rank-sort of each m's 32 bounds
    if (t < 96) {
        const int m = t >> 5, i = t & 31;
        const float v = sv[t];
        int pos = 0;
        for (int j = 0; j < 32; ++j) {
            const float u = sv[(m << 5) + j];
            pos += (u < v || (u == v && j < i)) ? 1 : 0;
        }
        spos[t] = pos;
        if (blockIdx.x == 0) gSortedB[(m << 5) + pos] = v;
    }
    __syncthreads();

    // hitmask per rank r: cond_l <=> pos(lo_l) < r && pos(hi_l) >= r
    if (t < 3 * NR) {
        const int m = t / NR, r = t - m * NR;
        unsigned mask = 0;
        for (int l = 0; l < 16; ++l) {
            const int plo = spos[(m << 5) + l];
            const int phi_ = spos[(m << 5) + 16 + l];
            if (plo < r && phi_ >= r) mask |= (1u << l);
        }
        sSH[m][r] = mask << (3 * m);    // into segment space
    }
    __syncthreads();

    // each thread fills table entries (grid covers all NTAB)
    for (int e = blockIdx.x * TPB + t; e < NTAB; e += gridDim.x * TPB) {
        const int r0 = e / (NR * NR);
        const int rem = e - r0 * NR * NR;
        const int r1 = rem / NR;
        const int r2 = rem - r1 * NR;
        const unsigned h0 = sSH[0][r0], h1 = sSH[1][r1], h2 = sSH[2][r2];
        const unsigned W2 = h2;
        const unsigned W1 = h1 & ~h2;
        const unsigned W0 = h0 & ~h1 & ~h2;
        float C0 = 0.f, S0 = 0.f, C1 = 0.f, S1 = 0.f, C2 = 0.f, S2 = 0.f, T = 0.f;
        for (int l = 0; l < 16; ++l) {
            if (W0 & (1u << l))       { C0 += svc[0][0][l]; S0 += svc[0][1][l]; T += svc[0][2][l]; }
            if (W1 & (1u << (3 + l))) { C1 += svc[1][0][l]; S1 += svc[1][1][l]; T += svc[1][2][l]; }
            if (W2 & (1u << (6 + l))) { C2 += svc[2][0][l]; S2 += svc[2][1][l]; T += svc[2][2][l]; }
        }
        Coef c;
        c.a = make_float4(C0, S0, C1, S1);
        c.b = make_float4(C2, S2, T, 0.0f);
        gC[e] = c;
    }
}

// ---------------- main ------------------------------------------------------
// rank = #{bounds < x} in [0,32], branchless binary search
__device__ __forceinline__ int rank32(const float* __restrict__ b, float xv) {
    int r = 0;
    if (b[15]    < xv) r = 16;
    if (b[r + 7] < xv) r += 8;
    if (b[r + 3] < xv) r += 4;
    if (b[r + 1] < xv) r += 2;
    if (b[r]     < xv) r += 1;
    if (b[r]     < xv) r += 1;
    return r;
}

__global__ void __launch_bounds__(TPB)
glm_main(const float* __restrict__ x,
         const float* __restrict__ weight,
         float* __restrict__ out, int batch) {
    __shared__ float sb[96];

    const int t = threadIdx.x;
    if (t < 96) sb[t] = gSortedB[t];
    if (blockIdx.x == 0 && t < 48) out[batch + t] = weight[t];  // weight tail
    __syncthreads();

    const int tid = blockIdx.x * TPB + t;
    const long long row0 = (long long)tid * RPT;
    if (row0 >= batch) return;

    const float4* xv = reinterpret_cast<const float4*>(x + row0 * 3);
    const float4 va = xv[0], vb = xv[1], vc = xv[2];
    const float X[RPT][3] = {
        {va.x, va.y, va.z}, {va.w, vb.x, vb.y},
        {vb.z, vb.w, vc.x}, {vc.y, vc.z, vc.w}
    };
    float Y[RPT];

#pragma unroll
    for (int r = 0; r < RPT; ++r) {
        const int ra = rank32(sb,      X[r][0]);
        const int rb = rank32(sb + 32, X[r][1]);
        const int rc = rank32(sb + 64, X[r][2]);
        const int e  = (ra * NR + rb) * NR + rc;
        const float4 u = __ldg(&gC[e].a);
        const float4 v = __ldg(&gC[e].b);
        float s0, c0, s1, c1, s2, c2;
        __sincosf(X[r][0], &s0, &c0);
        __sincosf(X[r][1], &s1, &c1);
        __sincosf(X[r][2], &s2, &c2);
        float y = v.z;
        y = fmaf(c0, u.x, y); y = fmaf(s0, u.y, y);
        y = fmaf(c1, u.z, y); y = fmaf(s1, u.w, y);
        y = fmaf(c2, v.x, y); y = fmaf(s2, v.y, y);
        Y[r] = y;
    }

    reinterpret_cast<float4*>(out)[tid] = make_float4(Y[0], Y[1], Y[2], Y[3]);
}

extern "C" void kernel_launch(void* const* d_in, const int* in_sizes, int n_in,
                              void* d_out, int out_size) {
    const float* x        = (const float*)d_in[0];
    const float* phis     = (const float*)d_in[1];
    const float* interval = (const float*)d_in[2];
    const float* weight   = (const float*)d_in[3];
    float* out = (float*)d_out;

    const int batch = in_sizes[0] / 3;
    const int n_threads = (batch + RPT - 1) / RPT;
    const int n_blocks  = (n_threads + TPB - 1) / TPB;

    setup_all<<<(NTAB + TPB - 1) / TPB, TPB>>>(phis, interval, weight);
    glm_main<<<n_blocks, TPB>>>(x, weight, out, batch);
}